// round 1
// baseline (speedup 1.0000x reference)
#include <cuda_runtime.h>

#define BN  8
#define CIN 64
#define HH  56
#define WW  56
#define HW  (HH*WW)
#define OCM 128

// Scratch offset maps (dy/dx/mask-logit conv outputs)
__device__ float g_om3[BN * 27 * HW];
__device__ float g_om5[BN * 75 * HW];

// ---------------------------------------------------------------------------
// Offset conv: om[b, och, y, x] = sum_{c,ky,kx} x[b,c,y+ky-P,x+kx-P]*ow[och,c,ky,kx] + ob[och]
// One block per (b, y). 256 threads: px = tid&63 (pixel), g = tid>>6 (channel group).
// ---------------------------------------------------------------------------
template<int K>
__global__ void __launch_bounds__(256) offset_conv_kernel(
    const float* __restrict__ x, const float* __restrict__ ow,
    const float* __restrict__ ob)
{
    constexpr int K2  = K * K;
    constexpr int K2r = (K2 + 3) & ~3;
    constexpr int P   = K / 2;
    constexpr int OCF = 3 * K2;
    constexpr int OCG = (OCF + 3) / 4;

    float* __restrict__ om = (K == 3) ? g_om3 : g_om5;

    __shared__ __align__(16) float ws[OCF * K2r];
    __shared__ float xs[K][64];

    const int b  = blockIdx.x / HH;
    const int y  = blockIdx.x % HH;
    const int tid = threadIdx.x;
    const int px = tid & 63;
    const int g  = tid >> 6;

    float acc[OCG];
#pragma unroll
    for (int j = 0; j < OCG; j++) acc[j] = 0.f;

    for (int c = 0; c < CIN; c++) {
        // weight slice for this input channel (padded taps -> 0)
        for (int i = tid; i < OCF * K2r; i += 256) {
            int och = i / K2r, tap = i - och * K2r;
            ws[i] = (tap < K2) ? ow[(och * CIN + c) * K2 + tap] : 0.f;
        }
        // input rows y-P .. y+P, cols shifted by -P
        for (int i = tid; i < K * 64; i += 256) {
            int r = i >> 6, col = i & 63;
            int yy = y - P + r, xx = col - P;
            float v = 0.f;
            if (yy >= 0 && yy < HH && xx >= 0 && xx < WW)
                v = x[((b * CIN + c) * HH + yy) * WW + xx];
            xs[r][col] = v;
        }
        __syncthreads();

        float xv[K2r];
#pragma unroll
        for (int t = 0; t < K2r; t++)
            xv[t] = (t < K2) ? xs[t / K][px + (t % K)] : 0.f;

#pragma unroll
        for (int j = 0; j < OCG; j++) {
            int och = g * OCG + j;
            if (och < OCF) {
                const float4* w4 = (const float4*)(ws + och * K2r);
#pragma unroll
                for (int t = 0; t < K2r / 4; t++) {
                    float4 wv = w4[t];
                    acc[j] = fmaf(xv[4*t+0], wv.x, acc[j]);
                    acc[j] = fmaf(xv[4*t+1], wv.y, acc[j]);
                    acc[j] = fmaf(xv[4*t+2], wv.z, acc[j]);
                    acc[j] = fmaf(xv[4*t+3], wv.w, acc[j]);
                }
            }
        }
        __syncthreads();
    }

    if (px < WW) {
#pragma unroll
        for (int j = 0; j < OCG; j++) {
            int och = g * OCG + j;
            if (och < OCF)
                om[((b * OCF + och) * HH + y) * WW + px] = acc[j] + ob[och];
        }
    }
}

// ---------------------------------------------------------------------------
// Deformable conv (+ fused 1x1 residual, biases, ReLU).
// One block per (b, y). Stage A precomputes bilinear corner indices and
// mask-folded corner weights (channel-independent). Per input channel c:
// gather cols[px][tap], load weight slice, register-tiled 128x56 GEMM slice.
// ---------------------------------------------------------------------------
template<int K, int CB>
__global__ void __launch_bounds__(256) deform_kernel(
    const float* __restrict__ x,  const float* __restrict__ w,
    const float* __restrict__ bias, const float* __restrict__ subw_g,
    const float* __restrict__ subb, float* __restrict__ out)
{
    constexpr int K2  = K * K;
    constexpr int K2r = (K2 + 3) & ~3;
    constexpr int P   = K / 2;

    const float* __restrict__ om = (K == 3) ? g_om3 : g_om5;

    extern __shared__ __align__(16) char smem_raw[];
    int4*   sidx = (int4*)smem_raw;                 // [K2*64] corner flat-indices
    float4* swt  = (float4*)(sidx + K2 * 64);       // [K2*64] corner weights (mask folded)
    float*  ws   = (float*)(swt + K2 * 64);         // [128*K2r] weight slice
    float*  cols = ws + OCM * K2r;                  // [64*K2r]  gathered samples
    float*  xrow = cols + 64 * K2r;                 // [64]      x row for 1x1 conv
    float*  subw = xrow + 64;                       // [128]     1x1 weights slice

    const int b  = blockIdx.x / HH;
    const int y  = blockIdx.x % HH;
    const int tid = threadIdx.x;
    const int px = tid & 63;
    const int g  = tid >> 6;

    // zero cols (pad taps stay 0; weights there are 0 too but avoid 0*garbage NaN)
    for (int i = tid; i < 64 * K2r; i += 256) cols[i] = 0.f;

    // ---- Stage A: sampling parameters, once per block ----
    for (int i = tid; i < K2 * WW; i += 256) {
        int tap = i / WW, pxx = i - tap * WW;
        int base = (b * 3 * K2) * HW + y * WW + pxx;
        float dy = om[base + tap * HW];
        float dx = om[base + (K2 + tap) * HW];
        float ml = om[base + (2 * K2 + tap) * HW];
        float m  = 1.f / (1.f + __expf(-ml));
        float sy = (float)(y   + tap / K - P) + dy;   // unpadded coords
        float sx = (float)(pxx + tap % K - P) + dx;
        float y0f = floorf(sy), x0f = floorf(sx);
        float ty = sy - y0f, tx = sx - x0f;
        int y0 = (int)y0f, x0 = (int)x0f, y1 = y0 + 1, x1 = x0 + 1;
        bool vy0 = (y0 >= 0) && (y0 < HH), vy1 = (y1 >= 0) && (y1 < HH);
        bool vx0 = (x0 >= 0) && (x0 < WW), vx1 = (x1 >= 0) && (x1 < WW);
        float w00 = (vy0 && vx0) ? (1.f - ty) * (1.f - tx) * m : 0.f;
        float w01 = (vy0 && vx1) ? (1.f - ty) * tx * m : 0.f;
        float w10 = (vy1 && vx0) ? ty * (1.f - tx) * m : 0.f;
        float w11 = (vy1 && vx1) ? ty * tx * m : 0.f;
        int cy0 = min(max(y0, 0), HH - 1) * WW;
        int cy1 = min(max(y1, 0), HH - 1) * WW;
        int cx0 = min(max(x0, 0), WW - 1);
        int cx1 = min(max(x1, 0), WW - 1);
        sidx[tap * 64 + pxx] = make_int4(cy0 + cx0, cy0 + cx1, cy1 + cx0, cy1 + cx1);
        swt [tap * 64 + pxx] = make_float4(w00, w01, w10, w11);
    }
    __syncthreads();

    float acc[32];
#pragma unroll
    for (int j = 0; j < 32; j++) acc[j] = 0.f;

    const float* xb = x + (size_t)b * CIN * HW;

    for (int c = 0; c < CIN; c++) {
        const float* Xc = xb + c * HW;
        // gather sampled column for this channel
        for (int i = tid; i < K2 * WW; i += 256) {
            int tap = i / WW, pxx = i - tap * WW;
            int4   id = sidx[tap * 64 + pxx];
            float4 wv = swt [tap * 64 + pxx];
            float v = wv.x * Xc[id.x] + wv.y * Xc[id.y]
                    + wv.z * Xc[id.z] + wv.w * Xc[id.w];
            cols[pxx * K2r + tap] = v;
        }
        // weight slice
        for (int i = tid; i < OCM * K2r; i += 256) {
            int och = i / K2r, tap = i - och * K2r;
            ws[i] = (tap < K2) ? w[(och * CIN + c) * K2 + tap] : 0.f;
        }
        if (tid < 64)  xrow[tid] = (tid < WW) ? Xc[y * WW + tid] : 0.f;
        if (tid >= 64 && tid < 192) subw[tid - 64] = subw_g[(tid - 64) * CIN + c];
        __syncthreads();

        float xsv = xrow[px];
        const float4* c4 = (const float4*)(cols + px * K2r);
        const float4* w4 = (const float4*)ws;
#pragma unroll
        for (int t = 0; t < K2r / 4; t++) {
            float4 xv = c4[t];
#pragma unroll
            for (int j = 0; j < 32; j++) {
                float4 wv = w4[(g * 32 + j) * (K2r / 4) + t];   // warp-broadcast
                acc[j] = fmaf(xv.x, wv.x, acc[j]);
                acc[j] = fmaf(xv.y, wv.y, acc[j]);
                acc[j] = fmaf(xv.z, wv.z, acc[j]);
                acc[j] = fmaf(xv.w, wv.w, acc[j]);
            }
        }
#pragma unroll
        for (int j = 0; j < 32; j++)
            acc[j] = fmaf(xsv, subw[g * 32 + j], acc[j]);   // fused 1x1 residual
        __syncthreads();
    }

    if (px < WW) {
#pragma unroll
        for (int j = 0; j < 32; j++) {
            int och = g * 32 + j;
            float v = acc[j] + bias[och] + subb[och];
            out[(((size_t)b * (2 * OCM) + CB + och) * HW) + y * WW + px] = fmaxf(v, 0.f);
        }
    }
}

static constexpr int deform_smem(int K) {
    int K2 = K * K, K2r = (K2 + 3) & ~3;
    return K2 * 64 * 16 * 2          // sidx + swt
         + OCM * K2r * 4             // ws
         + 64 * K2r * 4              // cols
         + 64 * 4 + OCM * 4;         // xrow + subw
}

extern "C" void kernel_launch(void* const* d_in, const int* in_sizes, int n_in,
                              void* d_out, int out_size)
{
    const float* x   = (const float*)d_in[0];
    const float* w3  = (const float*)d_in[1];
    const float* b3  = (const float*)d_in[2];
    const float* o3w = (const float*)d_in[3];
    const float* o3b = (const float*)d_in[4];
    const float* w5  = (const float*)d_in[5];
    const float* b5  = (const float*)d_in[6];
    const float* o5w = (const float*)d_in[7];
    const float* o5b = (const float*)d_in[8];
    const float* sw  = (const float*)d_in[9];
    const float* sb  = (const float*)d_in[10];
    float* out = (float*)d_out;

    constexpr int SM3 = deform_smem(3);   // 28,416 B
    constexpr int SM5 = deform_smem(5);   // 73,472 B (needs opt-in)
    cudaFuncSetAttribute((const void*)deform_kernel<3, 0>,
                         cudaFuncAttributeMaxDynamicSharedMemorySize, SM3);
    cudaFuncSetAttribute((const void*)deform_kernel<5, OCM>,
                         cudaFuncAttributeMaxDynamicSharedMemorySize, SM5);

    dim3 grid(BN * HH);
    offset_conv_kernel<3><<<grid, 256>>>(x, o3w, o3b);
    offset_conv_kernel<5><<<grid, 256>>>(x, o5w, o5b);
    deform_kernel<3, 0  ><<<grid, 256, SM3>>>(x, w3, b3, sw, sb, out);
    deform_kernel<5, OCM><<<grid, 256, SM5>>>(x, w5, b5, sw, sb, out);
}

// round 2
// speedup vs baseline: 1.2865x; 1.2865x over previous
#include <cuda_runtime.h>

#define BN  8
#define CIN 64
#define HH  56
#define WW  56
#define HW  (HH*WW)
#define OCM 128

// Scratch offset maps (dy/dx/mask-logit conv outputs)
__device__ float g_om3[BN * 27 * HW];
__device__ float g_om5[BN * 75 * HW];

typedef unsigned long long u64;

__device__ __forceinline__ u64 pack2(float lo, float hi) {
    u64 r; asm("mov.b64 %0, {%1, %2};" : "=l"(r) : "f"(lo), "f"(hi)); return r;
}
__device__ __forceinline__ void ffma2(u64 &d, u64 a, u64 b) {
    asm("fma.rn.f32x2 %0, %1, %2, %0;" : "+l"(d) : "l"(a), "l"(b));
}
__device__ __forceinline__ float2 unpack2(u64 v) {
    float2 f; asm("mov.b64 {%0, %1}, %2;" : "=f"(f.x), "=f"(f.y) : "l"(v)); return f;
}

// ---------------------------------------------------------------------------
// Offset conv. One block per (b, y). 256 threads = 8 warps.
// Warp g owns NP output-channel PAIRS (f32x2); lane owns pixels {lane, lane+32}.
// ---------------------------------------------------------------------------
template<int K>
__global__ void __launch_bounds__(256) offset_conv_kernel(
    const float* __restrict__ x, const float* __restrict__ ow,
    const float* __restrict__ ob)
{
    constexpr int K2  = K * K;
    constexpr int P   = K / 2;
    constexpr int OCF = 3 * K2;
    constexpr int NPT = (((OCF + 1) / 2) + 7) & ~7;   // total pairs, padded to 8
    constexpr int NP  = NPT / 8;                      // pairs per warp

    float* __restrict__ om = (K == 3) ? g_om3 : g_om5;

    __shared__ __align__(16) float2 ws2[NPT * K2];
    __shared__ float xs[K][72];

    const int b   = blockIdx.x / HH;
    const int y   = blockIdx.x % HH;
    const int tid = threadIdx.x;
    const int lane = tid & 31;
    const int g    = tid >> 5;

    u64 acc[NP * 2] = {};

    for (int c = 0; c < CIN; c++) {
        // paired weight slice for this input channel
        for (int i = tid; i < NPT * K2; i += 256) {
            int p = i / K2, tap = i - p * K2;
            int o0 = 2 * p, o1 = 2 * p + 1;
            float w0 = (o0 < OCF) ? ow[(o0 * CIN + c) * K2 + tap] : 0.f;
            float w1 = (o1 < OCF) ? ow[(o1 * CIN + c) * K2 + tap] : 0.f;
            ws2[i] = make_float2(w0, w1);
        }
        // input rows y-P .. y+P, cols shifted by -P (72-wide padded rows)
        for (int i = tid; i < K * 72; i += 256) {
            int r = i / 72, col = i - r * 72;
            int yy = y - P + r, xx = col - P;
            float v = 0.f;
            if (yy >= 0 && yy < HH && xx >= 0 && xx < WW)
                v = x[((b * CIN + c) * HH + yy) * WW + xx];
            xs[r][col] = v;
        }
        __syncthreads();

        const u64* wrow = (const u64*)(ws2 + g * NP * K2);
        for (int tap = 0; tap < K2; tap++) {
            int r = tap / K, dx = tap % K;
            float x0 = xs[r][lane + dx];
            float x1 = xs[r][lane + 32 + dx];
            u64 xa = pack2(x0, x0), xc = pack2(x1, x1);
#pragma unroll
            for (int j = 0; j < NP; j++) {
                u64 wv = wrow[j * K2 + tap];
                ffma2(acc[2 * j],     xa, wv);
                ffma2(acc[2 * j + 1], xc, wv);
            }
        }
        __syncthreads();
    }

#pragma unroll
    for (int j = 0; j < NP; j++) {
        float2 v0 = unpack2(acc[2 * j]);       // px0 : (o0, o1)
        float2 v1 = unpack2(acc[2 * j + 1]);   // px1
        int o0 = (g * NP + j) * 2, o1 = o0 + 1;
        int px1 = lane + 32;
        if (o0 < OCF) {
            float bb = ob[o0];
            om[((b * OCF + o0) * HH + y) * WW + lane] = v0.x + bb;
            if (px1 < WW) om[((b * OCF + o0) * HH + y) * WW + px1] = v1.x + bb;
        }
        if (o1 < OCF) {
            float bb = ob[o1];
            om[((b * OCF + o1) * HH + y) * WW + lane] = v0.y + bb;
            if (px1 < WW) om[((b * OCF + o1) * HH + y) * WW + px1] = v1.y + bb;
        }
    }
}

// ---------------------------------------------------------------------------
// Deformable conv (+ fused 1x1 residual, biases, ReLU).
// One block per (b, y), 256 threads = 8 warps. Warp g owns och pairs
// [g*8, g*8+8) (och g*16..g*16+15); lane owns pixels {lane, lane+32}.
// cols stored tap-major [tap][64] -> conflict-free scalar LDS.
// ---------------------------------------------------------------------------
template<int K, int CB>
__global__ void __launch_bounds__(256) deform_kernel(
    const float* __restrict__ x,  const float* __restrict__ w,
    const float* __restrict__ bias, const float* __restrict__ subw_g,
    const float* __restrict__ subb, float* __restrict__ out)
{
    constexpr int K2 = K * K;
    constexpr int P  = K / 2;

    const float* __restrict__ om = (K == 3) ? g_om3 : g_om5;

    extern __shared__ __align__(16) char smem_raw[];
    int4*   sidx  = (int4*)smem_raw;                 // [K2*64]
    float4* swt   = (float4*)(sidx + K2 * 64);       // [K2*64]
    float2* ws2   = (float2*)(swt + K2 * 64);        // [64 pairs * K2]
    float*  cols  = (float*)(ws2 + 64 * K2);         // [K2*64] tap-major
    float*  xrow  = cols + K2 * 64;                  // [64]
    float2* subw2 = (float2*)(xrow + 64);            // [64]

    const int b   = blockIdx.x / HH;
    const int y   = blockIdx.x % HH;
    const int tid = threadIdx.x;
    const int lane = tid & 31;
    const int g    = tid >> 5;

    // ---- Stage A: sampling parameters, once per block ----
    for (int i = tid; i < K2 * WW; i += 256) {
        int tap = i / WW, pxx = i - tap * WW;
        int base = (b * 3 * K2) * HW + y * WW + pxx;
        float dy = om[base + tap * HW];
        float dx = om[base + (K2 + tap) * HW];
        float ml = om[base + (2 * K2 + tap) * HW];
        float m  = 1.f / (1.f + __expf(-ml));
        float sy = (float)(y   + tap / K - P) + dy;
        float sx = (float)(pxx + tap % K - P) + dx;
        float y0f = floorf(sy), x0f = floorf(sx);
        float ty = sy - y0f, tx = sx - x0f;
        int y0 = (int)y0f, x0 = (int)x0f, y1 = y0 + 1, x1 = x0 + 1;
        bool vy0 = (y0 >= 0) && (y0 < HH), vy1 = (y1 >= 0) && (y1 < HH);
        bool vx0 = (x0 >= 0) && (x0 < WW), vx1 = (x1 >= 0) && (x1 < WW);
        float w00 = (vy0 && vx0) ? (1.f - ty) * (1.f - tx) * m : 0.f;
        float w01 = (vy0 && vx1) ? (1.f - ty) * tx * m : 0.f;
        float w10 = (vy1 && vx0) ? ty * (1.f - tx) * m : 0.f;
        float w11 = (vy1 && vx1) ? ty * tx * m : 0.f;
        int cy0 = min(max(y0, 0), HH - 1) * WW;
        int cy1 = min(max(y1, 0), HH - 1) * WW;
        int cx0 = min(max(x0, 0), WW - 1);
        int cx1 = min(max(x1, 0), WW - 1);
        sidx[tap * 64 + pxx] = make_int4(cy0 + cx0, cy0 + cx1, cy1 + cx0, cy1 + cx1);
        swt [tap * 64 + pxx] = make_float4(w00, w01, w10, w11);
    }
    __syncthreads();

    u64 acc[16] = {};
    const float* xb = x + (size_t)b * CIN * HW;

    for (int c = 0; c < CIN; c++) {
        const float* Xc = xb + c * HW;
        // gather sampled column for this channel (tap-major)
        for (int i = tid; i < K2 * WW; i += 256) {
            int tap = i / WW, pxx = i - tap * WW;
            int4   id = sidx[tap * 64 + pxx];
            float4 wv = swt [tap * 64 + pxx];
            cols[tap * 64 + pxx] = wv.x * Xc[id.x] + wv.y * Xc[id.y]
                                 + wv.z * Xc[id.z] + wv.w * Xc[id.w];
        }
        // paired weight slice
        for (int i = tid; i < 64 * K2; i += 256) {
            int p = i / K2, tap = i - p * K2;
            ws2[i] = make_float2(w[(2 * p * CIN + c) * K2 + tap],
                                 w[((2 * p + 1) * CIN + c) * K2 + tap]);
        }
        if (tid < 64) xrow[tid] = (tid < WW) ? Xc[y * WW + tid] : 0.f;
        if (tid >= 64 && tid < 128) {
            int p = tid - 64;
            subw2[p] = make_float2(subw_g[2 * p * CIN + c],
                                   subw_g[(2 * p + 1) * CIN + c]);
        }
        __syncthreads();

        const u64* wrow = (const u64*)(ws2 + g * 8 * K2);
        for (int tap = 0; tap < K2; tap++) {
            float c0 = cols[tap * 64 + lane];
            float c1 = cols[tap * 64 + lane + 32];
            u64 xa = pack2(c0, c0), xc = pack2(c1, c1);
#pragma unroll
            for (int j = 0; j < 8; j++) {
                u64 wv = wrow[j * K2 + tap];
                ffma2(acc[2 * j],     xa, wv);
                ffma2(acc[2 * j + 1], xc, wv);
            }
        }
        // fused 1x1 residual
        {
            float s0 = xrow[lane], s1 = xrow[lane + 32];
            u64 xa = pack2(s0, s0), xc = pack2(s1, s1);
            const u64* srow = (const u64*)(subw2 + g * 8);
#pragma unroll
            for (int j = 0; j < 8; j++) {
                u64 sv = srow[j];
                ffma2(acc[2 * j],     xa, sv);
                ffma2(acc[2 * j + 1], xc, sv);
            }
        }
        __syncthreads();
    }

#pragma unroll
    for (int j = 0; j < 8; j++) {
        int o0 = g * 16 + 2 * j, o1 = o0 + 1;
        float2 v0 = unpack2(acc[2 * j]);       // px0 : (o0, o1)
        float2 v1 = unpack2(acc[2 * j + 1]);   // px1
        float bb0 = bias[o0] + subb[o0];
        float bb1 = bias[o1] + subb[o1];
        size_t base0 = ((size_t)b * (2 * OCM) + CB + o0) * HW + y * WW;
        size_t base1 = ((size_t)b * (2 * OCM) + CB + o1) * HW + y * WW;
        out[base0 + lane] = fmaxf(v0.x + bb0, 0.f);
        out[base1 + lane] = fmaxf(v0.y + bb1, 0.f);
        if (lane + 32 < WW) {
            out[base0 + lane + 32] = fmaxf(v1.x + bb0, 0.f);
            out[base1 + lane + 32] = fmaxf(v1.y + bb1, 0.f);
        }
    }
}

static constexpr int deform_smem(int K) {
    int K2 = K * K;
    return K2 * 64 * 16 * 2          // sidx + swt
         + 64 * K2 * 8               // ws2 (pairs)
         + K2 * 64 * 4               // cols
         + 64 * 4 + 64 * 8;          // xrow + subw2
}

extern "C" void kernel_launch(void* const* d_in, const int* in_sizes, int n_in,
                              void* d_out, int out_size)
{
    const float* x   = (const float*)d_in[0];
    const float* w3  = (const float*)d_in[1];
    const float* b3  = (const float*)d_in[2];
    const float* o3w = (const float*)d_in[3];
    const float* o3b = (const float*)d_in[4];
    const float* w5  = (const float*)d_in[5];
    const float* b5  = (const float*)d_in[6];
    const float* o5w = (const float*)d_in[7];
    const float* o5b = (const float*)d_in[8];
    const float* sw  = (const float*)d_in[9];
    const float* sb  = (const float*)d_in[10];
    float* out = (float*)d_out;

    constexpr int SM3 = deform_smem(3);   // 26,112 B
    constexpr int SM5 = deform_smem(5);   // 71,168 B (needs opt-in)
    cudaFuncSetAttribute((const void*)deform_kernel<3, 0>,
                         cudaFuncAttributeMaxDynamicSharedMemorySize, SM3);
    cudaFuncSetAttribute((const void*)deform_kernel<5, OCM>,
                         cudaFuncAttributeMaxDynamicSharedMemorySize, SM5);

    dim3 grid(BN * HH);
    offset_conv_kernel<3><<<grid, 256>>>(x, o3w, o3b);
    offset_conv_kernel<5><<<grid, 256>>>(x, o5w, o5b);
    deform_kernel<3, 0  ><<<grid, 256, SM3>>>(x, w3, b3, sw, sb, out);
    deform_kernel<5, OCM><<<grid, 256, SM5>>>(x, w5, b5, sw, sb, out);
}

// round 3
// speedup vs baseline: 1.5230x; 1.1839x over previous
#include <cuda_runtime.h>

#define BN  8
#define CIN 64
#define HH  56
#define WW  56
#define HW  (HH*WW)
#define OCM 128

// Scratch offset maps (dy/dx/mask-logit conv outputs)
__device__ float g_om3[BN * 27 * HW];
__device__ float g_om5[BN * 75 * HW];

typedef unsigned long long u64;

__device__ __forceinline__ u64 pack2(float lo, float hi) {
    u64 r; asm("mov.b64 %0, {%1, %2};" : "=l"(r) : "f"(lo), "f"(hi)); return r;
}
__device__ __forceinline__ void ffma2(u64 &d, u64 a, u64 b) {
    asm("fma.rn.f32x2 %0, %1, %2, %0;" : "+l"(d) : "l"(a), "l"(b));
}
__device__ __forceinline__ float2 unpack2(u64 v) {
    float2 f; asm("mov.b64 {%0, %1}, %2;" : "=f"(f.x), "=f"(f.y) : "l"(v)); return f;
}

// ---------------------------------------------------------------------------
// Offset conv. One block per (b, row-pair). 256 threads = 8 warps.
// Warp g owns NP channel-pairs; lane owns 4 pixels {r0:lane, r0:lane+32,
// r1:lane, r1:lane+32}. Double-buffered smem, 1 sync per input channel.
// ---------------------------------------------------------------------------
template<int K>
__global__ void __launch_bounds__(256, 2) offset_conv_kernel(
    const float* __restrict__ x, const float* __restrict__ ow,
    const float* __restrict__ ob)
{
    constexpr int K2  = K * K;
    constexpr int P   = K / 2;
    constexpr int OCF = 3 * K2;
    constexpr int NPT = (((OCF + 1) / 2) + 7) & ~7;   // pairs, padded to 8
    constexpr int NP  = NPT / 8;
    constexpr int R   = K + 1;                        // rows needed for 2 out rows

    float* __restrict__ om = (K == 3) ? g_om3 : g_om5;

    __shared__ __align__(16) float2 ws2[2][NPT * K2];
    __shared__ float xs[2][R][72];

    const int b    = blockIdx.x / (HH / 2);
    const int yp   = blockIdx.x % (HH / 2);
    const int y0   = yp * 2;
    const int tid  = threadIdx.x;
    const int lane = tid & 31;
    const int g    = tid >> 5;

    u64 acc[NP * 4] = {};

    auto fill = [&](int c, int buf) {
        for (int i = tid; i < NPT * K2; i += 256) {
            int p = i / K2, tap = i - p * K2;
            int o0 = 2 * p, o1 = o0 + 1;
            float w0 = (o0 < OCF) ? ow[(o0 * CIN + c) * K2 + tap] : 0.f;
            float w1 = (o1 < OCF) ? ow[(o1 * CIN + c) * K2 + tap] : 0.f;
            ws2[buf][i] = make_float2(w0, w1);
        }
        for (int i = tid; i < R * 72; i += 256) {
            int r = i / 72, col = i - r * 72;
            int yy = y0 - P + r, xx = col - P;
            float v = 0.f;
            if (yy >= 0 && yy < HH && xx >= 0 && xx < WW)
                v = x[((b * CIN + c) * HH + yy) * WW + xx];
            xs[buf][r][col] = v;
        }
    };

    fill(0, 0);
    __syncthreads();

    for (int c = 0; c < CIN; c++) {
        int cur = c & 1;
        if (c + 1 < CIN) fill(c + 1, cur ^ 1);

        const u64* wrow = (const u64*)(ws2[cur] + g * NP * K2);
#pragma unroll
        for (int tap = 0; tap < K2; tap++) {
            int r = tap / K, dx = tap % K;
            float a0 = xs[cur][r][lane + dx];
            float a1 = xs[cur][r][lane + 32 + dx];
            float b0 = xs[cur][r + 1][lane + dx];
            float b1 = xs[cur][r + 1][lane + 32 + dx];
            u64 xa = pack2(a0, a0), xb_ = pack2(a1, a1);
            u64 xc = pack2(b0, b0), xd = pack2(b1, b1);
#pragma unroll
            for (int j = 0; j < NP; j++) {
                u64 wv = wrow[j * K2 + tap];
                ffma2(acc[4 * j],     xa, wv);
                ffma2(acc[4 * j + 1], xb_, wv);
                ffma2(acc[4 * j + 2], xc, wv);
                ffma2(acc[4 * j + 3], xd, wv);
            }
        }
        __syncthreads();
    }

#pragma unroll
    for (int j = 0; j < NP; j++) {
        int o0 = (g * NP + j) * 2, o1 = o0 + 1;
        float2 v00 = unpack2(acc[4 * j]);       // row0 px0 : (o0,o1)
        float2 v01 = unpack2(acc[4 * j + 1]);   // row0 px1
        float2 v10 = unpack2(acc[4 * j + 2]);   // row1 px0
        float2 v11 = unpack2(acc[4 * j + 3]);   // row1 px1
        int px1 = lane + 32;
        if (o0 < OCF) {
            float bb = ob[o0];
            float* p0 = om + ((b * OCF + o0) * HH + y0) * WW;
            p0[lane] = v00.x + bb;
            p0[WW + lane] = v10.x + bb;
            if (px1 < WW) { p0[px1] = v01.x + bb; p0[WW + px1] = v11.x + bb; }
        }
        if (o1 < OCF) {
            float bb = ob[o1];
            float* p1 = om + ((b * OCF + o1) * HH + y0) * WW;
            p1[lane] = v00.y + bb;
            p1[WW + lane] = v10.y + bb;
            if (px1 < WW) { p1[px1] = v01.y + bb; p1[WW + px1] = v11.y + bb; }
        }
    }
}

// ---------------------------------------------------------------------------
// Deformable conv (+ fused 1x1 residual, biases, ReLU).
// One block per (b, y), 256 threads = 8 warps, 3 blocks/SM.
// Double-buffered cols/weights, 1 sync per input channel; short4 corner idx.
// ---------------------------------------------------------------------------
template<int K, int CB>
__global__ void __launch_bounds__(256, 3) deform_kernel(
    const float* __restrict__ x,  const float* __restrict__ w,
    const float* __restrict__ bias, const float* __restrict__ subw_g,
    const float* __restrict__ subb, float* __restrict__ out)
{
    constexpr int K2  = K * K;
    constexpr int P   = K / 2;
    constexpr int NPX = K2 * 56;
    constexpr int NIT = (NPX + 255) / 256;
    constexpr int WIT = (64 * K2 + 255) / 256;

    const float* __restrict__ om = (K == 3) ? g_om3 : g_om5;

    extern __shared__ __align__(16) char smem_raw[];
    float4* swt   = (float4*)smem_raw;                // [NPX]
    short4* sidx  = (short4*)(swt + NPX);             // [NPX]
    float2* ws2   = (float2*)(sidx + NPX);            // [2][64*K2]
    float*  cols  = (float*)(ws2 + 2 * 64 * K2);      // [2][NPX]
    float*  xrow  = cols + 2 * NPX;                   // [2][64]
    float2* subw2 = (float2*)(xrow + 128);            // [2][64]

    const int b    = blockIdx.x / HH;
    const int y    = blockIdx.x % HH;
    const int tid  = threadIdx.x;
    const int lane = tid & 31;
    const int g    = tid >> 5;

    // ---- Stage A: sampling parameters, once per block ----
    for (int i = tid; i < NPX; i += 256) {
        int tap = i / 56, pxx = i - tap * 56;
        int base = (b * 3 * K2) * HW + y * WW + pxx;
        float dy = om[base + tap * HW];
        float dx = om[base + (K2 + tap) * HW];
        float ml = om[base + (2 * K2 + tap) * HW];
        float m  = 1.f / (1.f + __expf(-ml));
        float sy = (float)(y   + tap / K - P) + dy;
        float sx = (float)(pxx + tap % K - P) + dx;
        float y0f = floorf(sy), x0f = floorf(sx);
        float ty = sy - y0f, tx = sx - x0f;
        int y0 = (int)y0f, x0 = (int)x0f, y1 = y0 + 1, x1 = x0 + 1;
        bool vy0 = (y0 >= 0) && (y0 < HH), vy1 = (y1 >= 0) && (y1 < HH);
        bool vx0 = (x0 >= 0) && (x0 < WW), vx1 = (x1 >= 0) && (x1 < WW);
        float w00 = (vy0 && vx0) ? (1.f - ty) * (1.f - tx) * m : 0.f;
        float w01 = (vy0 && vx1) ? (1.f - ty) * tx * m : 0.f;
        float w10 = (vy1 && vx0) ? ty * (1.f - tx) * m : 0.f;
        float w11 = (vy1 && vx1) ? ty * tx * m : 0.f;
        int cy0 = min(max(y0, 0), HH - 1) * WW;
        int cy1 = min(max(y1, 0), HH - 1) * WW;
        int cx0 = min(max(x0, 0), WW - 1);
        int cx1 = min(max(x1, 0), WW - 1);
        swt [i] = make_float4(w00, w01, w10, w11);
        sidx[i] = make_short4((short)(cy0 + cx0), (short)(cy0 + cx1),
                              (short)(cy1 + cx0), (short)(cy1 + cx1));
    }

    const float* xb = x + (size_t)b * CIN * HW;

    auto fill = [&](int c, int buf) {
        const float* Xc = xb + c * HW;
        float* cb = cols + buf * NPX;
#pragma unroll
        for (int it = 0; it < NIT; it++) {
            int i = tid + it * 256;
            if (i < NPX) {
                short4 id = sidx[i];
                float4 wv = swt[i];
                cb[i] = wv.x * Xc[id.x] + wv.y * Xc[id.y]
                      + wv.z * Xc[id.z] + wv.w * Xc[id.w];
            }
        }
        float2* wb = ws2 + buf * 64 * K2;
#pragma unroll
        for (int it = 0; it < WIT; it++) {
            int i = tid + it * 256;
            if (i < 64 * K2) {
                int p = i / K2, tap = i - p * K2;
                wb[i] = make_float2(w[(2 * p * CIN + c) * K2 + tap],
                                    w[((2 * p + 1) * CIN + c) * K2 + tap]);
            }
        }
        if (tid < 64) {
            xrow[buf * 64 + tid] = (tid < WW) ? Xc[y * WW + tid] : 0.f;
        } else if (tid < 128) {
            int p = tid - 64;
            subw2[buf * 64 + p] = make_float2(subw_g[2 * p * CIN + c],
                                              subw_g[(2 * p + 1) * CIN + c]);
        }
    };

    __syncthreads();          // Stage A tables ready
    fill(0, 0);
    __syncthreads();

    u64 acc[16] = {};

    for (int c = 0; c < CIN; c++) {
        int cur = c & 1;
        if (c + 1 < CIN) fill(c + 1, cur ^ 1);

        const float* cc  = cols + cur * NPX;
        const u64* wrow  = (const u64*)(ws2 + cur * 64 * K2 + g * 8 * K2);
#pragma unroll
        for (int tap = 0; tap < K2; tap++) {
            float c0 = cc[tap * 56 + lane];
            float c1 = cc[tap * 56 + lane + 32];   // lanes >= 24 read junk; outputs discarded
            u64 xa = pack2(c0, c0), xc = pack2(c1, c1);
#pragma unroll
            for (int j = 0; j < 8; j++) {
                u64 wv = wrow[j * K2 + tap];
                ffma2(acc[2 * j],     xa, wv);
                ffma2(acc[2 * j + 1], xc, wv);
            }
        }
        // fused 1x1 residual
        {
            float s0 = xrow[cur * 64 + lane], s1 = xrow[cur * 64 + lane + 32];
            u64 xa = pack2(s0, s0), xc = pack2(s1, s1);
            const u64* srow = (const u64*)(subw2 + cur * 64 + g * 8);
#pragma unroll
            for (int j = 0; j < 8; j++) {
                u64 sv = srow[j];
                ffma2(acc[2 * j],     xa, sv);
                ffma2(acc[2 * j + 1], xc, sv);
            }
        }
        __syncthreads();
    }

#pragma unroll
    for (int j = 0; j < 8; j++) {
        int o0 = g * 16 + 2 * j, o1 = o0 + 1;
        float2 v0 = unpack2(acc[2 * j]);       // px0 : (o0, o1)
        float2 v1 = unpack2(acc[2 * j + 1]);   // px1
        float bb0 = bias[o0] + subb[o0];
        float bb1 = bias[o1] + subb[o1];
        size_t base0 = ((size_t)b * (2 * OCM) + CB + o0) * HW + y * WW;
        size_t base1 = ((size_t)b * (2 * OCM) + CB + o1) * HW + y * WW;
        out[base0 + lane] = fmaxf(v0.x + bb0, 0.f);
        out[base1 + lane] = fmaxf(v0.y + bb1, 0.f);
        if (lane + 32 < WW) {
            out[base0 + lane + 32] = fmaxf(v1.x + bb0, 0.f);
            out[base1 + lane + 32] = fmaxf(v1.y + bb1, 0.f);
        }
    }
}

static constexpr int deform_smem(int K) {
    int K2 = K * K, NPX = K2 * 56;
    return NPX * 16          // swt
         + NPX * 8           // sidx
         + 2 * 64 * K2 * 8   // ws2
         + 2 * NPX * 4       // cols
         + 128 * 4           // xrow
         + 128 * 8;          // subw2
}

extern "C" void kernel_launch(void* const* d_in, const int* in_sizes, int n_in,
                              void* d_out, int out_size)
{
    const float* x   = (const float*)d_in[0];
    const float* w3  = (const float*)d_in[1];
    const float* b3  = (const float*)d_in[2];
    const float* o3w = (const float*)d_in[3];
    const float* o3b = (const float*)d_in[4];
    const float* w5  = (const float*)d_in[5];
    const float* b5  = (const float*)d_in[6];
    const float* o5w = (const float*)d_in[7];
    const float* o5b = (const float*)d_in[8];
    const float* sw  = (const float*)d_in[9];
    const float* sb  = (const float*)d_in[10];
    float* out = (float*)d_out;

    constexpr int SM3 = deform_smem(3);   // 26,880 B
    constexpr int SM5 = deform_smem(5);   // 71,936 B
    cudaFuncSetAttribute((const void*)deform_kernel<3, 0>,
                         cudaFuncAttributeMaxDynamicSharedMemorySize, SM3);
    cudaFuncSetAttribute((const void*)deform_kernel<5, OCM>,
                         cudaFuncAttributeMaxDynamicSharedMemorySize, SM5);

    dim3 gridO(BN * (HH / 2));
    dim3 gridD(BN * HH);
    offset_conv_kernel<3><<<gridO, 256>>>(x, o3w, o3b);
    offset_conv_kernel<5><<<gridO, 256>>>(x, o5w, o5b);
    deform_kernel<3, 0  ><<<gridD, 256, SM3>>>(x, w3, b3, sw, sb, out);
    deform_kernel<5, OCM><<<gridD, 256, SM5>>>(x, w5, b5, sw, sb, out);
}